// round 13
// baseline (speedup 1.0000x reference)
#include <cuda_runtime.h>
#include <cuda_fp16.h>
#include <float.h>
#include <stdint.h>

#define Bb 4
#define Cc 256
#define C8 32
#define Hh 64
#define Ww 64
#define HW 4096

// ===================== helpers =============================================
__device__ __forceinline__ uint32_t smem_u32(const void* p) {
    uint32_t a;
    asm("{ .reg .u64 t; cvta.to.shared.u64 t, %1; cvt.u32.u64 %0, t; }"
        : "=r"(a) : "l"(p));
    return a;
}
#define SWZ128(off) ((off) ^ (((off) >> 3) & 0x70))

__device__ __forceinline__ void ldsm_x4(uint32_t (&r)[4], uint32_t addr) {
    asm volatile("ldmatrix.sync.aligned.m8n8.x4.shared.b16 {%0,%1,%2,%3}, [%4];"
                 : "=r"(r[0]), "=r"(r[1]), "=r"(r[2]), "=r"(r[3]) : "r"(addr));
}

__device__ __forceinline__ void mma_f16(float (&d)[4], const uint32_t (&a)[4],
                                        uint32_t b0, uint32_t b1) {
    asm volatile(
        "mma.sync.aligned.m16n8k16.row.col.f32.f16.f16.f32 "
        "{%0,%1,%2,%3}, {%4,%5,%6,%7}, {%8,%9}, {%0,%1,%2,%3};"
        : "+f"(d[0]), "+f"(d[1]), "+f"(d[2]), "+f"(d[3])
        : "r"(a[0]), "r"(a[1]), "r"(a[2]), "r"(a[3]), "r"(b0), "r"(b1));
}

#define CP_ASYNC16(dst, src) \
    asm volatile("cp.async.cg.shared.global [%0], [%1], 16;" :: "r"(dst), "l"(src) : "memory")
#define CP_COMMIT()  asm volatile("cp.async.commit_group;" ::: "memory")
#define CP_WAIT2()   asm volatile("cp.async.wait_group 2;" ::: "memory")
#define CP_WAIT0()   asm volatile("cp.async.wait_group 0;" ::: "memory")

__device__ __forceinline__ uint32_t pack_h2(float a, float b) {
    __half2 h = __floats2half2_rn(a, b);
    return *(uint32_t*)&h;
}

// ===================== scratch =============================================
__device__ float g_q[Bb * C8 * HW];
__device__ float g_k[Bb * C8 * HW];
__device__ float g_vt[Bb * HW * Cc];          // NHWC value: [b][p][c]
__device__ float g_pmax[Bb * 4 * HW];
__device__ int   g_parg[Bb * 4 * HW];
__device__ float g_S[Bb * HW];
__device__ int   g_arg[Bb * HW];
// NHWC fp16 single plane, zero halo (device globals zero-init; halo never written)
__device__ __half g_Xt[(size_t)Bb * 66 * 66 * 512];
// conv weights fp16 single plane: [tap9][o 256][c 512]
__device__ __half g_Wa[9 * 256 * 512];
// v weights fp16 single plane: [o 256][c 256]
__device__ __half g_Wv16[256 * 256];

// ===================== fused q+k projection (exact fp32) ====================
__global__ __launch_bounds__(256) void gemm_qk(const float* __restrict__ cross_x,
                                               const float* __restrict__ front_x,
                                               const float* __restrict__ Wq,
                                               const float* __restrict__ bq,
                                               const float* __restrict__ Wk,
                                               const float* __restrict__ bk) {
    __shared__ float Xs[16][128];
    __shared__ float Ws[16][36];
    const int b   = blockIdx.z;
    const int sel = blockIdx.y;                 // 0 -> q, 1 -> k
    const int hw0 = blockIdx.x * 128;
    const int tid = threadIdx.x;
    const int hid = tid & 31;
    const int oid = tid >> 5;

    const float* X    = sel ? front_x : cross_x;
    const float* Wm   = sel ? Wk : Wq;
    const float* bias = sel ? bk : bq;
    float*       out  = sel ? g_k : g_q;

    const float* xb = X + (size_t)b * Cc * HW;
    float acc[4][4];
#pragma unroll
    for (int n = 0; n < 4; n++)
#pragma unroll
        for (int m = 0; m < 4; m++) acc[n][m] = 0.f;

    for (int c0 = 0; c0 < Cc; c0 += 16) {
        __syncthreads();
#pragma unroll
        for (int r = 0; r < 8; r++) {
            int idx = tid + r * 256;
            int cc = idx >> 7, h = idx & 127;
            Xs[cc][h] = xb[(size_t)(c0 + cc) * HW + hw0 + h];
        }
#pragma unroll
        for (int r = 0; r < 2; r++) {
            int idx = tid + r * 256;
            int cc = idx >> 5, o = idx & 31;
            Ws[cc][o] = Wm[(size_t)o * Cc + c0 + cc];
        }
        __syncthreads();
#pragma unroll
        for (int cc = 0; cc < 16; cc++) {
            float4 wv = *(const float4*)&Ws[cc][oid * 4];
            float4 xv = *(const float4*)&Xs[cc][hid * 4];
            float wa[4] = {wv.x, wv.y, wv.z, wv.w};
            float xa[4] = {xv.x, xv.y, xv.z, xv.w};
#pragma unroll
            for (int n = 0; n < 4; n++)
#pragma unroll
                for (int m = 0; m < 4; m++) acc[n][m] += wa[n] * xa[m];
        }
    }
#pragma unroll
    for (int n = 0; n < 4; n++) {
        int o = oid * 4 + n;
        float bi = bias[o];
        float4 res;
        res.x = acc[n][0] + bi;
        res.y = acc[n][1] + bi;
        res.z = acc[n][2] + bi;
        res.w = acc[n][3] + bi;
        *(float4*)&out[(size_t)b * C8 * HW + (size_t)o * HW + hw0 + hid * 4] = res;
    }
}

// ===================== v projection: fp16 single-term mma.sync ==============
__global__ __launch_bounds__(256) void v_mma(const float* __restrict__ X,
                                             const float* __restrict__ bias,
                                             float* __restrict__ vt) {
    extern __shared__ char dynsm[];
    const int tid  = threadIdx.x;
    const int lane = tid & 31;
    const int wid  = tid >> 5;
    const int wm   = wid & 3;
    const int wn   = wid >> 2;
    const int n0   = blockIdx.x * 128;
    const int m0   = blockIdx.y * 128;
    const int b    = blockIdx.z;

    const uint32_t smbase = smem_u32(dynsm);
    const uint32_t tB = smbase;
    const uint32_t tA = smbase + 16384;

    float acc[2][8][4];
#pragma unroll
    for (int mt = 0; mt < 2; mt++)
#pragma unroll
        for (int j = 0; j < 8; j++)
#pragma unroll
            for (int e = 0; e < 4; e++) acc[mt][j][e] = 0.f;

    const int arow  = wm * 32 + (lane & 15);
    const int acolh = (lane >> 4) * 16;
    const int brow  = wn * 64 + (lane & 7) + ((lane >> 4) << 3);
    const int bcolh = ((lane >> 3) & 1) * 16;
    const int c2    = tid >> 5;

    for (int s = 0; s < 4; s++) {
        const int kc = s * 64;
        __syncthreads();
#pragma unroll
        for (int i = 0; i < 4; i++) {
            const int c = (i << 8) + tid;
            const int r = c >> 3, c16 = c & 7;
            uint32_t dst = tA + SWZ128((uint32_t)(r * 128 + c16 * 16));
            const __half* src = g_Wv16 + (size_t)(m0 + r) * 256 + kc + c16 * 8;
            CP_ASYNC16(dst, src);
        }
        CP_COMMIT();
#pragma unroll
        for (int cc = 0; cc < 4; cc++) {
            const int cp = c2 + 8 * cc;
            const size_t row0 = ((size_t)b * Cc + kc + 2 * cp) * HW + n0;
#pragma unroll
            for (int pb = 0; pb < 4; pb++) {
                const int px = lane + 32 * pb;
                float v0 = X[row0 + px];
                float v1 = X[row0 + HW + px];
                uint32_t off = SWZ128((uint32_t)(px * 128 + cp * 4));
                *(uint32_t*)(dynsm + off) = pack_h2(v0, v1);
            }
        }
        CP_WAIT0();
        __syncthreads();

#pragma unroll
        for (int ks = 0; ks < 4; ks++) {
            uint32_t ax[2][4], bx[4][4];
#pragma unroll
            for (int mt = 0; mt < 2; mt++) {
                uint32_t off = SWZ128((uint32_t)((arow + mt * 16) * 128 + ks * 32 + acolh));
                ldsm_x4(ax[mt], tA + off);
            }
#pragma unroll
            for (int j = 0; j < 4; j++) {
                uint32_t off = SWZ128((uint32_t)((brow + j * 16) * 128 + ks * 32 + bcolh));
                ldsm_x4(bx[j], tB + off);
            }
#pragma unroll
            for (int mt = 0; mt < 2; mt++)
#pragma unroll
                for (int j = 0; j < 4; j++) {
                    mma_f16(acc[mt][2 * j],     ax[mt], bx[j][0], bx[j][1]);
                    mma_f16(acc[mt][2 * j + 1], ax[mt], bx[j][2], bx[j][3]);
                }
        }
    }

    __syncthreads();
    float* smep = (float*)dynsm;
#pragma unroll
    for (int mt = 0; mt < 2; mt++) {
        const int o_lo = wm * 32 + mt * 16 + (lane >> 2);
        const int o_hi = o_lo + 8;
        const float bi_lo = bias[m0 + o_lo], bi_hi = bias[m0 + o_hi];
#pragma unroll
        for (int j = 0; j < 8; j++) {
            const int p = wn * 64 + j * 8 + 2 * (lane & 3);
            smep[p * 132 + o_lo]       = acc[mt][j][0] + bi_lo;
            smep[(p + 1) * 132 + o_lo] = acc[mt][j][1] + bi_lo;
            smep[p * 132 + o_hi]       = acc[mt][j][2] + bi_hi;
            smep[(p + 1) * 132 + o_hi] = acc[mt][j][3] + bi_hi;
        }
    }
    __syncthreads();
#pragma unroll
    for (int r = 0; r < 16; r++) {
        const int p = wid + 8 * r;
        float4 v = *(const float4*)&smep[p * 132 + lane * 4];
        *(float4*)&vt[((size_t)b * HW + n0 + p) * Cc + m0 + lane * 4] = v;
    }
}

// ===================== fused mid kernel (low-register branches only) ========
// blockIdx.x ranges (long blocks first):
//   [0,256)      energy rowmax/argmax (exact fp32), 256 queries/CTA
//   [256,2304)   fill g_Xt front channels (fp16)
//   [2304,2816)  prep conv weights (fp16)
#define SEG_EN  256
#define SEG_FI  2304
#define SEG_PW  2816
#define MID_SMEM 16896

__global__ __launch_bounds__(256) void mid_fused(const float* __restrict__ front_x,
                                                 const float* __restrict__ Wf) {
    extern __shared__ char dynsm[];
    const int tid  = threadIdx.x;
    const int bid  = blockIdx.x;

    if (bid < SEG_EN) {
        // ---------------- energy rowmax/argmax (exact fp32) ----------------
        float* ks = (float*)dynsm;                    // [32][128]
        const int jt = bid & 15;
        const int sp = (bid >> 4) & 3;
        const int b  = bid >> 6;
        const int j  = jt * 256 + tid;
        const float* qb = g_q + (size_t)b * C8 * HW;
        const float* kb = g_k + (size_t)b * C8 * HW;

        float qr[32];
#pragma unroll
        for (int c = 0; c < 32; c++) qr[c] = qb[c * HW + j];

        float best = -FLT_MAX;
        int   barg = 0;
        const int i0base = sp * 1024;

        for (int it = 0; it < 8; it++) {
            int i0 = i0base + it * 128;
            __syncthreads();
#pragma unroll
            for (int p = 0; p < 16; p++) {
                int idx = tid + p * 256;
                int cc = idx >> 7, h = idx & 127;
                ks[cc * 128 + h] = kb[cc * HW + i0 + h];
            }
            __syncthreads();
#pragma unroll 4
            for (int ii = 0; ii < 128; ii += 4) {
                float a0 = 0.f, a1 = 0.f, a2 = 0.f, a3 = 0.f;
#pragma unroll
                for (int c = 0; c < 32; c++) {
                    float4 kv = *(const float4*)&ks[c * 128 + ii];
                    a0 += kv.x * qr[c];
                    a1 += kv.y * qr[c];
                    a2 += kv.z * qr[c];
                    a3 += kv.w * qr[c];
                }
                if (a0 > best) { best = a0; barg = i0 + ii; }
                if (a1 > best) { best = a1; barg = i0 + ii + 1; }
                if (a2 > best) { best = a2; barg = i0 + ii + 2; }
                if (a3 > best) { best = a3; barg = i0 + ii + 3; }
            }
        }
        g_pmax[((size_t)b * 4 + sp) * HW + j] = best;
        g_parg[((size_t)b * 4 + sp) * HW + j] = barg;

    } else if (bid < SEG_FI) {
        // ---------------- fill g_Xt front channels (fp16) -------------------
        float* sm = (float*)dynsm;                    // [32][65]
        const int id = bid - SEG_EN;
        const int c0 = (id & 7) * 32;
        const int y  = (id >> 3) & 63;
        const int b  = id >> 9;
        const int x  = tid >> 2;
        const int g  = tid & 3;

#pragma unroll
        for (int pass = 0; pass < 8; pass++) {
            int idx = tid + pass * 256;
            int cc = idx >> 6, xx = idx & 63;
            sm[cc * 65 + xx] = front_x[((size_t)b * Cc + c0 + cc) * HW + y * Ww + xx];
        }
        __syncthreads();
        uint32_t hu[4];
#pragma unroll
        for (int e = 0; e < 4; e++)
            hu[e] = pack_h2(sm[(g * 8 + 2 * e) * 65 + x], sm[(g * 8 + 2 * e + 1) * 65 + x]);
        size_t base = ((size_t)(b * 66 + y + 1) * 66 + (x + 1)) * 512 + c0 + g * 8;
        *(uint4*)&g_Xt[base] = make_uint4(hu[0], hu[1], hu[2], hu[3]);

    } else {
        // ---------------- prep conv weights (fp16) --------------------------
        const int t = (bid - SEG_FI) * 256 + tid;     // < 131072
        const int o = t >> 9, i = t & 511;
#pragma unroll
        for (int k = 0; k < 9; k++) {
            float w = Wf[((size_t)o * 512 + i) * 9 + k];
            g_Wa[(((size_t)k) * 256 + o) * 512 + i] = __float2half_rn(w);
        }
    }
}

// ===================== reduce + fill T half =================================
__global__ void reduce_argmax() {
    int t = blockIdx.x * 256 + threadIdx.x;
    if (t >= Bb * HW) return;
    int b = t >> 12, j = t & 4095;
    float best = g_pmax[((size_t)b * 4) * HW + j];
    int   arg  = g_parg[((size_t)b * 4) * HW + j];
#pragma unroll
    for (int sp = 1; sp < 4; sp++) {
        float e = g_pmax[((size_t)b * 4 + sp) * HW + j];
        if (e > best) { best = e; arg = g_parg[((size_t)b * 4 + sp) * HW + j]; }
    }
    g_S[t] = best;
    g_arg[t] = arg;
}

__global__ __launch_bounds__(256) void fill_xt_T() {
    const int c0 = 256 + blockIdx.x * 32;
    const int y  = blockIdx.y;
    const int b  = blockIdx.z;
    const int tid = threadIdx.x;
    const int x  = tid >> 2;
    const int g  = tid & 3;

    const int a = g_arg[b * HW + y * Ww + x];
    const float* vp = g_vt + ((size_t)b * HW + a) * Cc + (c0 - 256) + g * 8;
    float4 u0 = *(const float4*)vp;
    float4 u1 = *(const float4*)(vp + 4);

    uint32_t hu[4];
    hu[0] = pack_h2(u0.x, u0.y);
    hu[1] = pack_h2(u0.z, u0.w);
    hu[2] = pack_h2(u1.x, u1.y);
    hu[3] = pack_h2(u1.z, u1.w);
    size_t base = ((size_t)(b * 66 + y + 1) * 66 + (x + 1)) * 512 + c0 + g * 8;
    *(uint4*)&g_Xt[base] = make_uint4(hu[0], hu[1], hu[2], hu[3]);
}

__global__ void prep_wv(const float* __restrict__ Wv) {
    int t = blockIdx.x * 256 + threadIdx.x;
    g_Wv16[t] = __float2half_rn(Wv[t]);
}

// ===================== mma.sync conv3x3 (fp16 single-term) + epilogue =======
#define STAGE 32768
#define NCHUNK 72

__device__ __forceinline__ void stage_chunk(uint32_t stg, int s, int b, int y0, int m0) {
    const int tap = s >> 3, kc = (s & 7) * 64;
    const int dy = tap / 3, dx = tap % 3;
    const int tid = threadIdx.x;
#pragma unroll
    for (int i = 0; i < 8; i++) {
        const int t = i >> 2;                          // 0:X 1:W
        const int u = ((i & 3) << 8) + tid;            // 0..1023
        const int r = u >> 3, c16 = u & 7;
        uint32_t dst = stg + (uint32_t)(t * 16384) + SWZ128((uint32_t)(r * 128 + c16 * 16));
        const void* src;
        if (t == 0) {
            const int ry = r >> 6, x = r & 63;
            src = &g_Xt[(((size_t)(b * 66 + y0 + ry + dy) * 66) + (x + dx)) * 512
                        + kc + c16 * 8];
        } else {
            src = &g_Wa[(((size_t)tap * 256) + m0 + r) * 512 + kc + c16 * 8];
        }
        CP_ASYNC16(dst, src);
    }
    CP_COMMIT();
}

__global__ __launch_bounds__(256, 1) void conv_mma(const float* __restrict__ front_x,
                                                   const float* __restrict__ bf,
                                                   float* __restrict__ out) {
    extern __shared__ char dynsm[];
    const int tid  = threadIdx.x;
    const int lane = tid & 31;
    const int wid  = tid >> 5;
    const int wm   = wid & 3;
    const int wn   = wid >> 2;
    const int nt   = blockIdx.x;
    const int m0   = blockIdx.y * 128;
    const int b    = blockIdx.z;
    const int y0   = nt * 2;
    const int n0   = nt * 128;

    const uint32_t smbase = smem_u32(dynsm);

    float acc[2][8][4];
#pragma unroll
    for (int mt = 0; mt < 2; mt++)
#pragma unroll
        for (int j = 0; j < 8; j++)
#pragma unroll
            for (int e = 0; e < 4; e++) acc[mt][j][e] = 0.f;

    const int arow  = wm * 32 + (lane & 15);
    const int acolh = (lane >> 4) * 16;
    const int brow  = wn * 64 + (lane & 7) + ((lane >> 4) << 3);
    const int bcolh = ((lane >> 3) & 1) * 16;

    stage_chunk(smbase,             0, b, y0, m0);
    stage_chunk(smbase + STAGE,     1, b, y0, m0);
    stage_chunk(smbase + 2 * STAGE, 2, b, y0, m0);

    for (int s = 0; s < NCHUNK; s++) {
        CP_WAIT2();
        __syncthreads();
        if (s + 3 < NCHUNK)
            stage_chunk(smbase + ((s + 3) & 3) * STAGE, s + 3, b, y0, m0);

        const uint32_t base = smbase + (s & 3) * STAGE;
        const uint32_t tB = base;
        const uint32_t tA = base + 16384;

#pragma unroll
        for (int ks = 0; ks < 4; ks++) {
            uint32_t ax[2][4], bx[4][4];
#pragma unroll
            for (int mt = 0; mt < 2; mt++) {
                uint32_t off = SWZ128((uint32_t)((arow + mt * 16) * 128 + ks * 32 + acolh));
                ldsm_x4(ax[mt], tA + off);
            }
#pragma unroll
            for (int j = 0; j < 4; j++) {
                uint32_t off = SWZ128((uint32_t)((brow + j * 16) * 128 + ks * 32 + bcolh));
                ldsm_x4(bx[j], tB + off);
            }
#pragma unroll
            for (int mt = 0; mt < 2; mt++)
#pragma unroll
                for (int j = 0; j < 4; j++) {
                    mma_f16(acc[mt][2 * j],     ax[mt], bx[j][0], bx[j][1]);
                    mma_f16(acc[mt][2 * j + 1], ax[mt], bx[j][2], bx[j][3]);
                }
        }
        __syncthreads();
    }

    const float* Sb = g_S + (size_t)b * HW;
#pragma unroll
    for (int mt = 0; mt < 2; mt++) {
        const int o_lo = m0 + wm * 32 + mt * 16 + (lane >> 2);
        const int o_hi = o_lo + 8;
        const float bi_lo = bf[o_lo], bi_hi = bf[o_hi];
#pragma unroll
        for (int j = 0; j < 8; j++) {
            const int p = n0 + wn * 64 + j * 8 + 2 * (lane & 3);
            const float2 Sv = *(const float2*)&Sb[p];
            const size_t off0 = ((size_t)(b * Cc + o_lo)) * HW + p;
            const size_t off1 = ((size_t)(b * Cc + o_hi)) * HW + p;
            const float2 f0 = *(const float2*)&front_x[off0];
            const float2 f1 = *(const float2*)&front_x[off1];
            float2 r0, r1;
            r0.x = f0.x + (acc[mt][j][0] + bi_lo) * Sv.x;
            r0.y = f0.y + (acc[mt][j][1] + bi_lo) * Sv.y;
            r1.x = f1.x + (acc[mt][j][2] + bi_hi) * Sv.x;
            r1.y = f1.y + (acc[mt][j][3] + bi_hi) * Sv.y;
            *(float2*)&out[off0] = r0;
            *(float2*)&out[off1] = r1;
        }
    }
}

// ===================== launch ==============================================
extern "C" void kernel_launch(void* const* d_in, const int* in_sizes, int n_in,
                              void* d_out, int out_size) {
    const float* front_x     = (const float*)d_in[0];
    const float* cross_x     = (const float*)d_in[1];
    const float* front_x_hat = (const float*)d_in[2];
    const float* Wq = (const float*)d_in[3];
    const float* bq = (const float*)d_in[4];
    const float* Wk = (const float*)d_in[5];
    const float* bk = (const float*)d_in[6];
    const float* Wv = (const float*)d_in[7];
    const float* bv = (const float*)d_in[8];
    const float* Wf = (const float*)d_in[9];
    const float* bf = (const float*)d_in[10];
    float* out = (float*)d_out;

    cudaFuncSetAttribute(conv_mma, cudaFuncAttributeMaxDynamicSharedMemorySize, 4 * STAGE);
    cudaFuncSetAttribute(v_mma, cudaFuncAttributeMaxDynamicSharedMemorySize, 128 * 132 * 4);
    cudaFuncSetAttribute(mid_fused, cudaFuncAttributeMaxDynamicSharedMemorySize, MID_SMEM);

    float* vt;
    cudaGetSymbolAddress((void**)&vt, g_vt);

    prep_wv<<<256, 256>>>(Wv);

    gemm_qk<<<dim3(32, 2, 4), 256>>>(cross_x, front_x, Wq, bq, Wk, bk);
    v_mma<<<dim3(32, 2, 4), 256, 128 * 132 * 4>>>(front_x_hat, bv, vt);

    mid_fused<<<SEG_PW, 256, MID_SMEM>>>(front_x, Wf);

    reduce_argmax<<<64, 256>>>();
    fill_xt_T<<<dim3(8, 64, 4), 256>>>();

    conv_mma<<<dim3(32, 2, 4), 256, 4 * STAGE>>>(front_x, bf, out);
}

// round 14
// speedup vs baseline: 1.1512x; 1.1512x over previous
#include <cuda_runtime.h>
#include <cuda_fp16.h>
#include <float.h>
#include <stdint.h>

#define Bb 4
#define Cc 256
#define C8 32
#define Hh 64
#define Ww 64
#define HW 4096

// ===================== helpers =============================================
__device__ __forceinline__ uint32_t smem_u32(const void* p) {
    uint32_t a;
    asm("{ .reg .u64 t; cvta.to.shared.u64 t, %1; cvt.u32.u64 %0, t; }"
        : "=r"(a) : "l"(p));
    return a;
}
#define SWZ128(off) ((off) ^ (((off) >> 3) & 0x70))

__device__ __forceinline__ void ldsm_x4(uint32_t (&r)[4], uint32_t addr) {
    asm volatile("ldmatrix.sync.aligned.m8n8.x4.shared.b16 {%0,%1,%2,%3}, [%4];"
                 : "=r"(r[0]), "=r"(r[1]), "=r"(r[2]), "=r"(r[3]) : "r"(addr));
}

__device__ __forceinline__ void mma_f16(float (&d)[4], const uint32_t (&a)[4],
                                        uint32_t b0, uint32_t b1) {
    asm volatile(
        "mma.sync.aligned.m16n8k16.row.col.f32.f16.f16.f32 "
        "{%0,%1,%2,%3}, {%4,%5,%6,%7}, {%8,%9}, {%0,%1,%2,%3};"
        : "+f"(d[0]), "+f"(d[1]), "+f"(d[2]), "+f"(d[3])
        : "r"(a[0]), "r"(a[1]), "r"(a[2]), "r"(a[3]), "r"(b0), "r"(b1));
}

#define CP_ASYNC16(dst, src) \
    asm volatile("cp.async.cg.shared.global [%0], [%1], 16;" :: "r"(dst), "l"(src) : "memory")
#define CP_COMMIT()  asm volatile("cp.async.commit_group;" ::: "memory")
#define CP_WAIT2()   asm volatile("cp.async.wait_group 2;" ::: "memory")
#define CP_WAIT0()   asm volatile("cp.async.wait_group 0;" ::: "memory")

__device__ __forceinline__ uint32_t pack_h2(float a, float b) {
    __half2 h = __floats2half2_rn(a, b);
    return *(uint32_t*)&h;
}

// ===================== scratch =============================================
__device__ float g_q[Bb * C8 * HW];
__device__ float g_k[Bb * C8 * HW];
__device__ float g_vt[Bb * HW * Cc];          // NHWC value: [b][p][c]
__device__ float g_pmax[Bb * 4 * HW];
__device__ int   g_parg[Bb * 4 * HW];
__device__ float g_S[Bb * HW];
// NHWC fp16 single plane, zero halo (device globals zero-init; halo never written)
__device__ __half g_Xt[(size_t)Bb * 66 * 66 * 512];
// conv weights fp16 single plane: [tap9][o 256][c 512]
__device__ __half g_Wa[9 * 256 * 512];
// v weights fp16 single plane: [o 256][c 256]
__device__ __half g_Wv16[256 * 256];

// ===================== fused q+k projection (exact fp32, 64-px tiles) =======
__global__ __launch_bounds__(256) void gemm_qk(const float* __restrict__ cross_x,
                                               const float* __restrict__ front_x,
                                               const float* __restrict__ Wq,
                                               const float* __restrict__ bq,
                                               const float* __restrict__ Wk,
                                               const float* __restrict__ bk) {
    __shared__ float Xs[16][64];
    __shared__ float Ws[16][36];
    const int b   = blockIdx.z;
    const int sel = blockIdx.y;                 // 0 -> q, 1 -> k
    const int hw0 = blockIdx.x * 64;
    const int tid = threadIdx.x;
    const int hid = tid & 31;                   // 32 px-groups of 2
    const int oid = tid >> 5;                   // 8 o-groups of 4

    const float* X    = sel ? front_x : cross_x;
    const float* Wm   = sel ? Wk : Wq;
    const float* bias = sel ? bk : bq;
    float*       out  = sel ? g_k : g_q;

    const float* xb = X + (size_t)b * Cc * HW;
    float acc[4][2];
#pragma unroll
    for (int n = 0; n < 4; n++)
#pragma unroll
        for (int m = 0; m < 2; m++) acc[n][m] = 0.f;

    for (int c0 = 0; c0 < Cc; c0 += 16) {
        __syncthreads();
#pragma unroll
        for (int r = 0; r < 4; r++) {            // 16*64/256 = 4 per thread
            int idx = tid + r * 256;
            int cc = idx >> 6, h = idx & 63;
            Xs[cc][h] = xb[(size_t)(c0 + cc) * HW + hw0 + h];
        }
#pragma unroll
        for (int r = 0; r < 2; r++) {            // 16*32/256 = 2 per thread
            int idx = tid + r * 256;
            int cc = idx >> 5, o = idx & 31;
            Ws[cc][o] = Wm[(size_t)o * Cc + c0 + cc];
        }
        __syncthreads();
#pragma unroll
        for (int cc = 0; cc < 16; cc++) {
            float4 wv = *(const float4*)&Ws[cc][oid * 4];
            float2 xv = *(const float2*)&Xs[cc][hid * 2];
            float wa[4] = {wv.x, wv.y, wv.z, wv.w};
            float xa[2] = {xv.x, xv.y};
#pragma unroll
            for (int n = 0; n < 4; n++)
#pragma unroll
                for (int m = 0; m < 2; m++) acc[n][m] += wa[n] * xa[m];
        }
    }
#pragma unroll
    for (int n = 0; n < 4; n++) {
        int o = oid * 4 + n;
        float bi = bias[o];
        float2 res;
        res.x = acc[n][0] + bi;
        res.y = acc[n][1] + bi;
        *(float2*)&out[(size_t)b * C8 * HW + (size_t)o * HW + hw0 + hid * 2] = res;
    }
}

// ===================== fused mid kernel =====================================
// blockIdx.x ranges (long blocks first):
//   [0,256)      energy rowmax/argmax (exact fp32), 256 queries/CTA
//   [256,512)    v projection (fp16 mma.sync)
//   [512,2560)   fill g_Xt front channels (fp16)
//   [2560,3072)  prep conv weights (fp16)
#define SEG_EN  256
#define SEG_VM  512
#define SEG_FI  2560
#define SEG_PW  3072
#define MID_SMEM 67584

__global__ __launch_bounds__(256) void mid_fused(const float* __restrict__ front_x,
                                                 const float* __restrict__ Xhat,
                                                 const float* __restrict__ bv,
                                                 const float* __restrict__ Wf) {
    extern __shared__ char dynsm[];
    const int tid  = threadIdx.x;
    const int bid  = blockIdx.x;

    if (bid < SEG_EN) {
        // ---------------- energy rowmax/argmax (exact fp32) ----------------
        float* ks = (float*)dynsm;                    // [32][128]
        const int jt = bid & 15;
        const int sp = (bid >> 4) & 3;
        const int b  = bid >> 6;
        const int j  = jt * 256 + tid;
        const float* qb = g_q + (size_t)b * C8 * HW;
        const float* kb = g_k + (size_t)b * C8 * HW;

        float qr[32];
#pragma unroll
        for (int c = 0; c < 32; c++) qr[c] = qb[c * HW + j];

        float best = -FLT_MAX;
        int   barg = 0;
        const int i0base = sp * 1024;

        for (int it = 0; it < 8; it++) {
            int i0 = i0base + it * 128;
            __syncthreads();
#pragma unroll
            for (int p = 0; p < 16; p++) {
                int idx = tid + p * 256;
                int cc = idx >> 7, h = idx & 127;
                ks[cc * 128 + h] = kb[cc * HW + i0 + h];
            }
            __syncthreads();
#pragma unroll 4
            for (int ii = 0; ii < 128; ii += 4) {
                float a0 = 0.f, a1 = 0.f, a2 = 0.f, a3 = 0.f;
#pragma unroll
                for (int c = 0; c < 32; c++) {
                    float4 kv = *(const float4*)&ks[c * 128 + ii];
                    a0 += kv.x * qr[c];
                    a1 += kv.y * qr[c];
                    a2 += kv.z * qr[c];
                    a3 += kv.w * qr[c];
                }
                if (a0 > best) { best = a0; barg = i0 + ii; }
                if (a1 > best) { best = a1; barg = i0 + ii + 1; }
                if (a2 > best) { best = a2; barg = i0 + ii + 2; }
                if (a3 > best) { best = a3; barg = i0 + ii + 3; }
            }
        }
        g_pmax[((size_t)b * 4 + sp) * HW + j] = best;
        g_parg[((size_t)b * 4 + sp) * HW + j] = barg;

    } else if (bid < SEG_VM) {
        // ---------------- v projection: fp16 mma.sync -----------------------
        const int id   = bid - SEG_EN;
        const int lane = tid & 31;
        const int wid  = tid >> 5;
        const int wm   = wid & 3;
        const int wn   = wid >> 2;
        const int n0   = (id & 31) * 128;
        const int m0   = ((id >> 5) & 1) * 128;
        const int b    = id >> 6;

        const uint32_t smbase = smem_u32(dynsm);
        const uint32_t tB = smbase;
        const uint32_t tA = smbase + 16384;

        float acc[2][8][4];
#pragma unroll
        for (int mt = 0; mt < 2; mt++)
#pragma unroll
            for (int j = 0; j < 8; j++)
#pragma unroll
                for (int e = 0; e < 4; e++) acc[mt][j][e] = 0.f;

        const int arow  = wm * 32 + (lane & 15);
        const int acolh = (lane >> 4) * 16;
        const int brow  = wn * 64 + (lane & 7) + ((lane >> 4) << 3);
        const int bcolh = ((lane >> 3) & 1) * 16;
        const int c2    = tid >> 5;

        for (int s = 0; s < 4; s++) {
            const int kc = s * 64;
            __syncthreads();
#pragma unroll
            for (int i = 0; i < 4; i++) {
                const int c = (i << 8) + tid;
                const int r = c >> 3, c16 = c & 7;
                uint32_t dst = tA + SWZ128((uint32_t)(r * 128 + c16 * 16));
                const __half* src = g_Wv16 + (size_t)(m0 + r) * 256 + kc + c16 * 8;
                CP_ASYNC16(dst, src);
            }
            CP_COMMIT();
#pragma unroll
            for (int cc = 0; cc < 4; cc++) {
                const int cp = c2 + 8 * cc;
                const size_t row0 = ((size_t)b * Cc + kc + 2 * cp) * HW + n0;
#pragma unroll
                for (int pb = 0; pb < 4; pb++) {
                    const int px = lane + 32 * pb;
                    float v0 = Xhat[row0 + px];
                    float v1 = Xhat[row0 + HW + px];
                    uint32_t off = SWZ128((uint32_t)(px * 128 + cp * 4));
                    *(uint32_t*)(dynsm + off) = pack_h2(v0, v1);
                }
            }
            CP_WAIT0();
            __syncthreads();

#pragma unroll
            for (int ks2 = 0; ks2 < 4; ks2++) {
                uint32_t ax[2][4], bx[4][4];
#pragma unroll
                for (int mt = 0; mt < 2; mt++) {
                    uint32_t off = SWZ128((uint32_t)((arow + mt * 16) * 128 + ks2 * 32 + acolh));
                    ldsm_x4(ax[mt], tA + off);
                }
#pragma unroll
                for (int j = 0; j < 4; j++) {
                    uint32_t off = SWZ128((uint32_t)((brow + j * 16) * 128 + ks2 * 32 + bcolh));
                    ldsm_x4(bx[j], tB + off);
                }
#pragma unroll
                for (int mt = 0; mt < 2; mt++)
#pragma unroll
                    for (int j = 0; j < 4; j++) {
                        mma_f16(acc[mt][2 * j],     ax[mt], bx[j][0], bx[j][1]);
                        mma_f16(acc[mt][2 * j + 1], ax[mt], bx[j][2], bx[j][3]);
                    }
            }
        }

        __syncthreads();
        float* smep = (float*)dynsm;
#pragma unroll
        for (int mt = 0; mt < 2; mt++) {
            const int o_lo = wm * 32 + mt * 16 + (lane >> 2);
            const int o_hi = o_lo + 8;
            const float bi_lo = bv[m0 + o_lo], bi_hi = bv[m0 + o_hi];
#pragma unroll
            for (int j = 0; j < 8; j++) {
                const int p = wn * 64 + j * 8 + 2 * (lane & 3);
                smep[p * 132 + o_lo]       = acc[mt][j][0] + bi_lo;
                smep[(p + 1) * 132 + o_lo] = acc[mt][j][1] + bi_lo;
                smep[p * 132 + o_hi]       = acc[mt][j][2] + bi_hi;
                smep[(p + 1) * 132 + o_hi] = acc[mt][j][3] + bi_hi;
            }
        }
        __syncthreads();
#pragma unroll
        for (int r = 0; r < 16; r++) {
            const int p = wid + 8 * r;
            float4 v = *(const float4*)&smep[p * 132 + lane * 4];
            *(float4*)&g_vt[((size_t)b * HW + n0 + p) * Cc + m0 + lane * 4] = v;
        }

    } else if (bid < SEG_FI) {
        // ---------------- fill g_Xt front channels (fp16) -------------------
        float* sm = (float*)dynsm;                    // [32][65]
        const int id = bid - SEG_VM;
        const int c0 = (id & 7) * 32;
        const int y  = (id >> 3) & 63;
        const int b  = id >> 9;
        const int x  = tid >> 2;
        const int g  = tid & 3;

#pragma unroll
        for (int pass = 0; pass < 8; pass++) {
            int idx = tid + pass * 256;
            int cc = idx >> 6, xx = idx & 63;
            sm[cc * 65 + xx] = front_x[((size_t)b * Cc + c0 + cc) * HW + y * Ww + xx];
        }
        __syncthreads();
        uint32_t hu[4];
#pragma unroll
        for (int e = 0; e < 4; e++)
            hu[e] = pack_h2(sm[(g * 8 + 2 * e) * 65 + x], sm[(g * 8 + 2 * e + 1) * 65 + x]);
        size_t base = ((size_t)(b * 66 + y + 1) * 66 + (x + 1)) * 512 + c0 + g * 8;
        *(uint4*)&g_Xt[base] = make_uint4(hu[0], hu[1], hu[2], hu[3]);

    } else {
        // ---------------- prep conv weights (fp16) --------------------------
        const int t = (bid - SEG_FI) * 256 + tid;     // < 131072
        const int o = t >> 9, i = t & 511;
#pragma unroll
        for (int k = 0; k < 9; k++) {
            float w = Wf[((size_t)o * 512 + i) * 9 + k];
            g_Wa[(((size_t)k) * 256 + o) * 512 + i] = __float2half_rn(w);
        }
    }
}

// ===================== fill T half + inline split-reduce =====================
__global__ __launch_bounds__(256) void fill_xt_T() {
    const int cx = blockIdx.x;                    // 0..7, channel chunk
    const int c0 = 256 + cx * 32;
    const int y  = blockIdx.y;
    const int b  = blockIdx.z;
    const int tid = threadIdx.x;
    const int x  = tid >> 2;
    const int g  = tid & 3;
    const int j  = y * Ww + x;

    // inline reduce of the 4 key-splits (same order/compare as before)
    float best = g_pmax[((size_t)b * 4) * HW + j];
    int   arg  = g_parg[((size_t)b * 4) * HW + j];
#pragma unroll
    for (int sp = 1; sp < 4; sp++) {
        float e = g_pmax[((size_t)b * 4 + sp) * HW + j];
        if (e > best) { best = e; arg = g_parg[((size_t)b * 4 + sp) * HW + j]; }
    }
    if (cx == 0 && g == 0) g_S[(size_t)b * HW + j] = best;

    const float* vp = g_vt + ((size_t)b * HW + arg) * Cc + (c0 - 256) + g * 8;
    float4 u0 = *(const float4*)vp;
    float4 u1 = *(const float4*)(vp + 4);

    uint32_t hu[4];
    hu[0] = pack_h2(u0.x, u0.y);
    hu[1] = pack_h2(u0.z, u0.w);
    hu[2] = pack_h2(u1.x, u1.y);
    hu[3] = pack_h2(u1.z, u1.w);
    size_t base = ((size_t)(b * 66 + y + 1) * 66 + (x + 1)) * 512 + c0 + g * 8;
    *(uint4*)&g_Xt[base] = make_uint4(hu[0], hu[1], hu[2], hu[3]);
}

__global__ void prep_wv(const float* __restrict__ Wv) {
    int t = blockIdx.x * 256 + threadIdx.x;
    g_Wv16[t] = __float2half_rn(Wv[t]);
}

// ===================== mma.sync conv3x3 (fp16 single-term) + epilogue =======
#define STAGE 32768
#define NCHUNK 72

__device__ __forceinline__ void stage_chunk(uint32_t stg, int s, int b, int y0, int m0) {
    const int tap = s >> 3, kc = (s & 7) * 64;
    const int dy = tap / 3, dx = tap % 3;
    const int tid = threadIdx.x;
#pragma unroll
    for (int i = 0; i < 8; i++) {
        const int t = i >> 2;                          // 0:X 1:W
        const int u = ((i & 3) << 8) + tid;            // 0..1023
        const int r = u >> 3, c16 = u & 7;
        uint32_t dst = stg + (uint32_t)(t * 16384) + SWZ128((uint32_t)(r * 128 + c16 * 16));
        const void* src;
        if (t == 0) {
            const int ry = r >> 6, x = r & 63;
            src = &g_Xt[(((size_t)(b * 66 + y0 + ry + dy) * 66) + (x + dx)) * 512
                        + kc + c16 * 8];
        } else {
            src = &g_Wa[(((size_t)tap * 256) + m0 + r) * 512 + kc + c16 * 8];
        }
        CP_ASYNC16(dst, src);
    }
    CP_COMMIT();
}

__global__ __launch_bounds__(256, 1) void conv_mma(const float* __restrict__ front_x,
                                                   const float* __restrict__ bf,
                                                   float* __restrict__ out) {
    extern __shared__ char dynsm[];
    const int tid  = threadIdx.x;
    const int lane = tid & 31;
    const int wid  = tid >> 5;
    const int wm   = wid & 3;
    const int wn   = wid >> 2;
    const int nt   = blockIdx.x;
    const int m0   = blockIdx.y * 128;
    const int b    = blockIdx.z;
    const int y0   = nt * 2;
    const int n0   = nt * 128;

    const uint32_t smbase = smem_u32(dynsm);

    float acc[2][8][4];
#pragma unroll
    for (int mt = 0; mt < 2; mt++)
#pragma unroll
        for (int j = 0; j < 8; j++)
#pragma unroll
            for (int e = 0; e < 4; e++) acc[mt][j][e] = 0.f;

    const int arow  = wm * 32 + (lane & 15);
    const int acolh = (lane >> 4) * 16;
    const int brow  = wn * 64 + (lane & 7) + ((lane >> 4) << 3);
    const int bcolh = ((lane >> 3) & 1) * 16;

    stage_chunk(smbase,             0, b, y0, m0);
    stage_chunk(smbase + STAGE,     1, b, y0, m0);
    stage_chunk(smbase + 2 * STAGE, 2, b, y0, m0);

    for (int s = 0; s < NCHUNK; s++) {
        CP_WAIT2();
        __syncthreads();
        if (s + 3 < NCHUNK)
            stage_chunk(smbase + ((s + 3) & 3) * STAGE, s + 3, b, y0, m0);

        const uint32_t base = smbase + (s & 3) * STAGE;
        const uint32_t tB = base;
        const uint32_t tA = base + 16384;

#pragma unroll
        for (int ks = 0; ks < 4; ks++) {
            uint32_t ax[2][4], bx[4][4];
#pragma unroll
            for (int mt = 0; mt < 2; mt++) {
                uint32_t off = SWZ128((uint32_t)((arow + mt * 16) * 128 + ks * 32 + acolh));
                ldsm_x4(ax[mt], tA + off);
            }
#pragma unroll
            for (int j = 0; j < 4; j++) {
                uint32_t off = SWZ128((uint32_t)((brow + j * 16) * 128 + ks * 32 + bcolh));
                ldsm_x4(bx[j], tB + off);
            }
#pragma unroll
            for (int mt = 0; mt < 2; mt++)
#pragma unroll
                for (int j = 0; j < 4; j++) {
                    mma_f16(acc[mt][2 * j],     ax[mt], bx[j][0], bx[j][1]);
                    mma_f16(acc[mt][2 * j + 1], ax[mt], bx[j][2], bx[j][3]);
                }
        }
        __syncthreads();
    }

    const float* Sb = g_S + (size_t)b * HW;
#pragma unroll
    for (int mt = 0; mt < 2; mt++) {
        const int o_lo = m0 + wm * 32 + mt * 16 + (lane >> 2);
        const int o_hi = o_lo + 8;
        const float bi_lo = bf[o_lo], bi_hi = bf[o_hi];
#pragma unroll
        for (int j = 0; j < 8; j++) {
            const int p = n0 + wn * 64 + j * 8 + 2 * (lane & 3);
            const float2 Sv = *(const float2*)&Sb[p];
            const size_t off0 = ((size_t)(b * Cc + o_lo)) * HW + p;
            const size_t off1 = ((size_t)(b * Cc + o_hi)) * HW + p;
            const float2 f0 = *(const float2*)&front_x[off0];
            const float2 f1 = *(const float2*)&front_x[off1];
            float2 r0, r1;
            r0.x = f0.x + (acc[mt][j][0] + bi_lo) * Sv.x;
            r0.y = f0.y + (acc[mt][j][1] + bi_lo) * Sv.y;
            r1.x = f1.x + (acc[mt][j][2] + bi_hi) * Sv.x;
            r1.y = f1.y + (acc[mt][j][3] + bi_hi) * Sv.y;
            *(float2*)&out[off0] = r0;
            *(float2*)&out[off1] = r1;
        }
    }
}

// ===================== launch ==============================================
extern "C" void kernel_launch(void* const* d_in, const int* in_sizes, int n_in,
                              void* d_out, int out_size) {
    const float* front_x     = (const float*)d_in[0];
    const float* cross_x     = (const float*)d_in[1];
    const float* front_x_hat = (const float*)d_in[2];
    const float* Wq = (const float*)d_in[3];
    const float* bq = (const float*)d_in[4];
    const float* Wk = (const float*)d_in[5];
    const float* bk = (const float*)d_in[6];
    const float* Wv = (const float*)d_in[7];
    const float* bv = (const float*)d_in[8];
    const float* Wf = (const float*)d_in[9];
    const float* bf = (const float*)d_in[10];
    float* out = (float*)d_out;

    cudaFuncSetAttribute(conv_mma, cudaFuncAttributeMaxDynamicSharedMemorySize, 4 * STAGE);
    cudaFuncSetAttribute(mid_fused, cudaFuncAttributeMaxDynamicSharedMemorySize, MID_SMEM);

    prep_wv<<<256, 256>>>(Wv);

    gemm_qk<<<dim3(64, 2, 4), 256>>>(cross_x, front_x, Wq, bq, Wk, bk);

    mid_fused<<<SEG_PW, 256, MID_SMEM>>>(front_x, front_x_hat, bv, Wf);

    fill_xt_T<<<dim3(8, 64, 4), 256>>>();

    conv_mma<<<dim3(32, 2, 4), 256, 4 * STAGE>>>(front_x, bf, out);
}

// round 15
// speedup vs baseline: 1.1761x; 1.0216x over previous
#include <cuda_runtime.h>
#include <cuda_fp16.h>
#include <float.h>
#include <stdint.h>

#define Bb 4
#define Cc 256
#define C8 32
#define Hh 64
#define Ww 64
#define HW 4096

// ===================== helpers =============================================
__device__ __forceinline__ uint32_t smem_u32(const void* p) {
    uint32_t a;
    asm("{ .reg .u64 t; cvta.to.shared.u64 t, %1; cvt.u32.u64 %0, t; }"
        : "=r"(a) : "l"(p));
    return a;
}
#define SWZ128(off) ((off) ^ (((off) >> 3) & 0x70))

__device__ __forceinline__ void ldsm_x4(uint32_t (&r)[4], uint32_t addr) {
    asm volatile("ldmatrix.sync.aligned.m8n8.x4.shared.b16 {%0,%1,%2,%3}, [%4];"
                 : "=r"(r[0]), "=r"(r[1]), "=r"(r[2]), "=r"(r[3]) : "r"(addr));
}

__device__ __forceinline__ void mma_f16(float (&d)[4], const uint32_t (&a)[4],
                                        uint32_t b0, uint32_t b1) {
    asm volatile(
        "mma.sync.aligned.m16n8k16.row.col.f32.f16.f16.f32 "
        "{%0,%1,%2,%3}, {%4,%5,%6,%7}, {%8,%9}, {%0,%1,%2,%3};"
        : "+f"(d[0]), "+f"(d[1]), "+f"(d[2]), "+f"(d[3])
        : "r"(a[0]), "r"(a[1]), "r"(a[2]), "r"(a[3]), "r"(b0), "r"(b1));
}

#define CP_ASYNC16(dst, src) \
    asm volatile("cp.async.cg.shared.global [%0], [%1], 16;" :: "r"(dst), "l"(src) : "memory")
#define CP_COMMIT()  asm volatile("cp.async.commit_group;" ::: "memory")
#define CP_WAIT2()   asm volatile("cp.async.wait_group 2;" ::: "memory")
#define CP_WAIT0()   asm volatile("cp.async.wait_group 0;" ::: "memory")

__device__ __forceinline__ uint32_t pack_h2(float a, float b) {
    __half2 h = __floats2half2_rn(a, b);
    return *(uint32_t*)&h;
}

// ===================== scratch =============================================
__device__ float g_q[Bb * C8 * HW];
__device__ float g_k[Bb * C8 * HW];
__device__ float g_vt[Bb * HW * Cc];          // NHWC value: [b][p][c]
__device__ float g_pmax[Bb * 4 * HW];
__device__ int   g_parg[Bb * 4 * HW];
__device__ float g_S[Bb * HW];
// NHWC fp16 single plane, zero halo (device globals zero-init; halo never written)
__device__ __half g_Xt[(size_t)Bb * 66 * 66 * 512];
// conv weights fp16 single plane: [tap9][o 256][c 512]
__device__ __half g_Wa[9 * 256 * 512];
// v weights fp16 single plane: [o 256][c 256]
__device__ __half g_Wv16[256 * 256];

// ===================== fused q+k projection (exact fp32, 128-px tiles) ======
__global__ __launch_bounds__(256) void gemm_qk(const float* __restrict__ cross_x,
                                               const float* __restrict__ front_x,
                                               const float* __restrict__ Wq,
                                               const float* __restrict__ bq,
                                               const float* __restrict__ Wk,
                                               const float* __restrict__ bk) {
    __shared__ float Xs[16][128];
    __shared__ float Ws[16][36];
    const int b   = blockIdx.z;
    const int sel = blockIdx.y;                 // 0 -> q, 1 -> k
    const int hw0 = blockIdx.x * 128;
    const int tid = threadIdx.x;
    const int hid = tid & 31;
    const int oid = tid >> 5;

    const float* X    = sel ? front_x : cross_x;
    const float* Wm   = sel ? Wk : Wq;
    const float* bias = sel ? bk : bq;
    float*       out  = sel ? g_k : g_q;

    const float* xb = X + (size_t)b * Cc * HW;
    float acc[4][4];
#pragma unroll
    for (int n = 0; n < 4; n++)
#pragma unroll
        for (int m = 0; m < 4; m++) acc[n][m] = 0.f;

    for (int c0 = 0; c0 < Cc; c0 += 16) {
        __syncthreads();
#pragma unroll
        for (int r = 0; r < 8; r++) {
            int idx = tid + r * 256;
            int cc = idx >> 7, h = idx & 127;
            Xs[cc][h] = xb[(size_t)(c0 + cc) * HW + hw0 + h];
        }
#pragma unroll
        for (int r = 0; r < 2; r++) {
            int idx = tid + r * 256;
            int cc = idx >> 5, o = idx & 31;
            Ws[cc][o] = Wm[(size_t)o * Cc + c0 + cc];
        }
        __syncthreads();
#pragma unroll
        for (int cc = 0; cc < 16; cc++) {
            float4 wv = *(const float4*)&Ws[cc][oid * 4];
            float4 xv = *(const float4*)&Xs[cc][hid * 4];
            float wa[4] = {wv.x, wv.y, wv.z, wv.w};
            float xa[4] = {xv.x, xv.y, xv.z, xv.w};
#pragma unroll
            for (int n = 0; n < 4; n++)
#pragma unroll
                for (int m = 0; m < 4; m++) acc[n][m] += wa[n] * xa[m];
        }
    }
#pragma unroll
    for (int n = 0; n < 4; n++) {
        int o = oid * 4 + n;
        float bi = bias[o];
        float4 res;
        res.x = acc[n][0] + bi;
        res.y = acc[n][1] + bi;
        res.z = acc[n][2] + bi;
        res.w = acc[n][3] + bi;
        *(float4*)&out[(size_t)b * C8 * HW + (size_t)o * HW + hw0 + hid * 4] = res;
    }
}

// ===================== fused mid kernel =====================================
// blockIdx.x ranges (long blocks first):
//   [0,256)      energy rowmax/argmax (exact fp32), 256 queries/CTA
//   [256,512)    v projection (fp16 mma.sync)
//   [512,2560)   fill g_Xt front channels (fp16)
//   [2560,3072)  prep conv weights (fp16)
#define SEG_EN  256
#define SEG_VM  512
#define SEG_FI  2560
#define SEG_PW  3072
#define MID_SMEM 67584

__global__ __launch_bounds__(256) void mid_fused(const float* __restrict__ front_x,
                                                 const float* __restrict__ Xhat,
                                                 const float* __restrict__ bv,
                                                 const float* __restrict__ Wf) {
    extern __shared__ char dynsm[];
    const int tid  = threadIdx.x;
    const int bid  = blockIdx.x;

    if (bid < SEG_EN) {
        // ---------------- energy rowmax/argmax (exact fp32) ----------------
        float* ks = (float*)dynsm;                    // [32][128]
        const int jt = bid & 15;
        const int sp = (bid >> 4) & 3;
        const int b  = bid >> 6;
        const int j  = jt * 256 + tid;
        const float* qb = g_q + (size_t)b * C8 * HW;
        const float* kb = g_k + (size_t)b * C8 * HW;

        float qr[32];
#pragma unroll
        for (int c = 0; c < 32; c++) qr[c] = qb[c * HW + j];

        float best = -FLT_MAX;
        int   barg = 0;
        const int i0base = sp * 1024;

        for (int it = 0; it < 8; it++) {
            int i0 = i0base + it * 128;
            __syncthreads();
#pragma unroll
            for (int p = 0; p < 16; p++) {
                int idx = tid + p * 256;
                int cc = idx >> 7, h = idx & 127;
                ks[cc * 128 + h] = kb[cc * HW + i0 + h];
            }
            __syncthreads();
#pragma unroll 4
            for (int ii = 0; ii < 128; ii += 4) {
                float a0 = 0.f, a1 = 0.f, a2 = 0.f, a3 = 0.f;
#pragma unroll
                for (int c = 0; c < 32; c++) {
                    float4 kv = *(const float4*)&ks[c * 128 + ii];
                    a0 += kv.x * qr[c];
                    a1 += kv.y * qr[c];
                    a2 += kv.z * qr[c];
                    a3 += kv.w * qr[c];
                }
                if (a0 > best) { best = a0; barg = i0 + ii; }
                if (a1 > best) { best = a1; barg = i0 + ii + 1; }
                if (a2 > best) { best = a2; barg = i0 + ii + 2; }
                if (a3 > best) { best = a3; barg = i0 + ii + 3; }
            }
        }
        g_pmax[((size_t)b * 4 + sp) * HW + j] = best;
        g_parg[((size_t)b * 4 + sp) * HW + j] = barg;

    } else if (bid < SEG_VM) {
        // ---------------- v projection: fp16 mma.sync -----------------------
        const int id   = bid - SEG_EN;
        const int lane = tid & 31;
        const int wid  = tid >> 5;
        const int wm   = wid & 3;
        const int wn   = wid >> 2;
        const int n0   = (id & 31) * 128;
        const int m0   = ((id >> 5) & 1) * 128;
        const int b    = id >> 6;

        const uint32_t smbase = smem_u32(dynsm);
        const uint32_t tB = smbase;
        const uint32_t tA = smbase + 16384;

        float acc[2][8][4];
#pragma unroll
        for (int mt = 0; mt < 2; mt++)
#pragma unroll
            for (int j = 0; j < 8; j++)
#pragma unroll
                for (int e = 0; e < 4; e++) acc[mt][j][e] = 0.f;

        const int arow  = wm * 32 + (lane & 15);
        const int acolh = (lane >> 4) * 16;
        const int brow  = wn * 64 + (lane & 7) + ((lane >> 4) << 3);
        const int bcolh = ((lane >> 3) & 1) * 16;
        const int c2    = tid >> 5;

        for (int s = 0; s < 4; s++) {
            const int kc = s * 64;
            __syncthreads();
#pragma unroll
            for (int i = 0; i < 4; i++) {
                const int c = (i << 8) + tid;
                const int r = c >> 3, c16 = c & 7;
                uint32_t dst = tA + SWZ128((uint32_t)(r * 128 + c16 * 16));
                const __half* src = g_Wv16 + (size_t)(m0 + r) * 256 + kc + c16 * 8;
                CP_ASYNC16(dst, src);
            }
            CP_COMMIT();
#pragma unroll
            for (int cc = 0; cc < 4; cc++) {
                const int cp = c2 + 8 * cc;
                const size_t row0 = ((size_t)b * Cc + kc + 2 * cp) * HW + n0;
#pragma unroll
                for (int pb = 0; pb < 4; pb++) {
                    const int px = lane + 32 * pb;
                    float v0 = Xhat[row0 + px];
                    float v1 = Xhat[row0 + HW + px];
                    uint32_t off = SWZ128((uint32_t)(px * 128 + cp * 4));
                    *(uint32_t*)(dynsm + off) = pack_h2(v0, v1);
                }
            }
            CP_WAIT0();
            __syncthreads();

#pragma unroll
            for (int ks2 = 0; ks2 < 4; ks2++) {
                uint32_t ax[2][4], bx[4][4];
#pragma unroll
                for (int mt = 0; mt < 2; mt++) {
                    uint32_t off = SWZ128((uint32_t)((arow + mt * 16) * 128 + ks2 * 32 + acolh));
                    ldsm_x4(ax[mt], tA + off);
                }
#pragma unroll
                for (int j = 0; j < 4; j++) {
                    uint32_t off = SWZ128((uint32_t)((brow + j * 16) * 128 + ks2 * 32 + bcolh));
                    ldsm_x4(bx[j], tB + off);
                }
#pragma unroll
                for (int mt = 0; mt < 2; mt++)
#pragma unroll
                    for (int j = 0; j < 4; j++) {
                        mma_f16(acc[mt][2 * j],     ax[mt], bx[j][0], bx[j][1]);
                        mma_f16(acc[mt][2 * j + 1], ax[mt], bx[j][2], bx[j][3]);
                    }
            }
        }

        __syncthreads();
        float* smep = (float*)dynsm;
#pragma unroll
        for (int mt = 0; mt < 2; mt++) {
            const int o_lo = wm * 32 + mt * 16 + (lane >> 2);
            const int o_hi = o_lo + 8;
            const float bi_lo = bv[m0 + o_lo], bi_hi = bv[m0 + o_hi];
#pragma unroll
            for (int j = 0; j < 8; j++) {
                const int p = wn * 64 + j * 8 + 2 * (lane & 3);
                smep[p * 132 + o_lo]       = acc[mt][j][0] + bi_lo;
                smep[(p + 1) * 132 + o_lo] = acc[mt][j][1] + bi_lo;
                smep[p * 132 + o_hi]       = acc[mt][j][2] + bi_hi;
                smep[(p + 1) * 132 + o_hi] = acc[mt][j][3] + bi_hi;
            }
        }
        __syncthreads();
#pragma unroll
        for (int r = 0; r < 16; r++) {
            const int p = wid + 8 * r;
            float4 v = *(const float4*)&smep[p * 132 + lane * 4];
            *(float4*)&g_vt[((size_t)b * HW + n0 + p) * Cc + m0 + lane * 4] = v;
        }

    } else if (bid < SEG_FI) {
        // ---------------- fill g_Xt front channels (fp16) -------------------
        float* sm = (float*)dynsm;                    // [32][65]
        const int id = bid - SEG_VM;
        const int c0 = (id & 7) * 32;
        const int y  = (id >> 3) & 63;
        const int b  = id >> 9;
        const int x  = tid >> 2;
        const int g  = tid & 3;

#pragma unroll
        for (int pass = 0; pass < 8; pass++) {
            int idx = tid + pass * 256;
            int cc = idx >> 6, xx = idx & 63;
            sm[cc * 65 + xx] = front_x[((size_t)b * Cc + c0 + cc) * HW + y * Ww + xx];
        }
        __syncthreads();
        uint32_t hu[4];
#pragma unroll
        for (int e = 0; e < 4; e++)
            hu[e] = pack_h2(sm[(g * 8 + 2 * e) * 65 + x], sm[(g * 8 + 2 * e + 1) * 65 + x]);
        size_t base = ((size_t)(b * 66 + y + 1) * 66 + (x + 1)) * 512 + c0 + g * 8;
        *(uint4*)&g_Xt[base] = make_uint4(hu[0], hu[1], hu[2], hu[3]);

    } else {
        // ---------------- prep conv weights (fp16) --------------------------
        const int t = (bid - SEG_FI) * 256 + tid;     // < 131072
        const int o = t >> 9, i = t & 511;
#pragma unroll
        for (int k = 0; k < 9; k++) {
            float w = Wf[((size_t)o * 512 + i) * 9 + k];
            g_Wa[(((size_t)k) * 256 + o) * 512 + i] = __float2half_rn(w);
        }
    }
}

// ===================== fill T half + inline split-reduce =====================
__global__ __launch_bounds__(256) void fill_xt_T() {
    const int cx = blockIdx.x;                    // 0..7, channel chunk
    const int c0 = 256 + cx * 32;
    const int y  = blockIdx.y;
    const int b  = blockIdx.z;
    const int tid = threadIdx.x;
    const int x  = tid >> 2;
    const int g  = tid & 3;
    const int j  = y * Ww + x;

    // inline reduce of the 4 key-splits (same order/compare as before)
    float best = g_pmax[((size_t)b * 4) * HW + j];
    int   arg  = g_parg[((size_t)b * 4) * HW + j];
#pragma unroll
    for (int sp = 1; sp < 4; sp++) {
        float e = g_pmax[((size_t)b * 4 + sp) * HW + j];
        if (e > best) { best = e; arg = g_parg[((size_t)b * 4 + sp) * HW + j]; }
    }
    if (cx == 0 && g == 0) g_S[(size_t)b * HW + j] = best;

    const float* vp = g_vt + ((size_t)b * HW + arg) * Cc + (c0 - 256) + g * 8;
    float4 u0 = *(const float4*)vp;
    float4 u1 = *(const float4*)(vp + 4);

    uint32_t hu[4];
    hu[0] = pack_h2(u0.x, u0.y);
    hu[1] = pack_h2(u0.z, u0.w);
    hu[2] = pack_h2(u1.x, u1.y);
    hu[3] = pack_h2(u1.z, u1.w);
    size_t base = ((size_t)(b * 66 + y + 1) * 66 + (x + 1)) * 512 + c0 + g * 8;
    *(uint4*)&g_Xt[base] = make_uint4(hu[0], hu[1], hu[2], hu[3]);
}

__global__ void prep_wv(const float* __restrict__ Wv) {
    int t = blockIdx.x * 256 + threadIdx.x;
    g_Wv16[t] = __float2half_rn(Wv[t]);
}

// ===================== mma.sync conv3x3 (fp16 single-term) + epilogue =======
#define STAGE 32768
#define NCHUNK 72

__device__ __forceinline__ void stage_chunk(uint32_t stg, int s, int b, int y0, int m0) {
    const int tap = s >> 3, kc = (s & 7) * 64;
    const int dy = tap / 3, dx = tap % 3;
    const int tid = threadIdx.x;
#pragma unroll
    for (int i = 0; i < 8; i++) {
        const int t = i >> 2;                          // 0:X 1:W
        const int u = ((i & 3) << 8) + tid;            // 0..1023
        const int r = u >> 3, c16 = u & 7;
        uint32_t dst = stg + (uint32_t)(t * 16384) + SWZ128((uint32_t)(r * 128 + c16 * 16));
        const void* src;
        if (t == 0) {
            const int ry = r >> 6, x = r & 63;
            src = &g_Xt[(((size_t)(b * 66 + y0 + ry + dy) * 66) + (x + dx)) * 512
                        + kc + c16 * 8];
        } else {
            src = &g_Wa[(((size_t)tap * 256) + m0 + r) * 512 + kc + c16 * 8];
        }
        CP_ASYNC16(dst, src);
    }
    CP_COMMIT();
}

__global__ __launch_bounds__(256, 1) void conv_mma(const float* __restrict__ front_x,
                                                   const float* __restrict__ bf,
                                                   float* __restrict__ out) {
    extern __shared__ char dynsm[];
    const int tid  = threadIdx.x;
    const int lane = tid & 31;
    const int wid  = tid >> 5;
    const int wm   = wid & 3;
    const int wn   = wid >> 2;
    const int nt   = blockIdx.x;
    const int m0   = blockIdx.y * 128;
    const int b    = blockIdx.z;
    const int y0   = nt * 2;
    const int n0   = nt * 128;

    const uint32_t smbase = smem_u32(dynsm);

    float acc[2][8][4];
#pragma unroll
    for (int mt = 0; mt < 2; mt++)
#pragma unroll
        for (int j = 0; j < 8; j++)
#pragma unroll
            for (int e = 0; e < 4; e++) acc[mt][j][e] = 0.f;

    const int arow  = wm * 32 + (lane & 15);
    const int acolh = (lane >> 4) * 16;
    const int brow  = wn * 64 + (lane & 7) + ((lane >> 4) << 3);
    const int bcolh = ((lane >> 3) & 1) * 16;

    stage_chunk(smbase,             0, b, y0, m0);
    stage_chunk(smbase + STAGE,     1, b, y0, m0);
    stage_chunk(smbase + 2 * STAGE, 2, b, y0, m0);

    for (int s = 0; s < NCHUNK; s++) {
        CP_WAIT2();
        __syncthreads();
        if (s + 3 < NCHUNK)
            stage_chunk(smbase + ((s + 3) & 3) * STAGE, s + 3, b, y0, m0);

        const uint32_t base = smbase + (s & 3) * STAGE;
        const uint32_t tB = base;
        const uint32_t tA = base + 16384;

#pragma unroll
        for (int ks = 0; ks < 4; ks++) {
            uint32_t ax[2][4], bx[4][4];
#pragma unroll
            for (int mt = 0; mt < 2; mt++) {
                uint32_t off = SWZ128((uint32_t)((arow + mt * 16) * 128 + ks * 32 + acolh));
                ldsm_x4(ax[mt], tA + off);
            }
#pragma unroll
            for (int j = 0; j < 4; j++) {
                uint32_t off = SWZ128((uint32_t)((brow + j * 16) * 128 + ks * 32 + bcolh));
                ldsm_x4(bx[j], tB + off);
            }
#pragma unroll
            for (int mt = 0; mt < 2; mt++)
#pragma unroll
                for (int j = 0; j < 4; j++) {
                    mma_f16(acc[mt][2 * j],     ax[mt], bx[j][0], bx[j][1]);
                    mma_f16(acc[mt][2 * j + 1], ax[mt], bx[j][2], bx[j][3]);
                }
        }
        __syncthreads();
    }

    const float* Sb = g_S + (size_t)b * HW;
#pragma unroll
    for (int mt = 0; mt < 2; mt++) {
        const int o_lo = m0 + wm * 32 + mt * 16 + (lane >> 2);
        const int o_hi = o_lo + 8;
        const float bi_lo = bf[o_lo], bi_hi = bf[o_hi];
#pragma unroll
        for (int j = 0; j < 8; j++) {
            const int p = n0 + wn * 64 + j * 8 + 2 * (lane & 3);
            const float2 Sv = *(const float2*)&Sb[p];
            const size_t off0 = ((size_t)(b * Cc + o_lo)) * HW + p;
            const size_t off1 = ((size_t)(b * Cc + o_hi)) * HW + p;
            const float2 f0 = *(const float2*)&front_x[off0];
            const float2 f1 = *(const float2*)&front_x[off1];
            float2 r0, r1;
            r0.x = f0.x + (acc[mt][j][0] + bi_lo) * Sv.x;
            r0.y = f0.y + (acc[mt][j][1] + bi_lo) * Sv.y;
            r1.x = f1.x + (acc[mt][j][2] + bi_hi) * Sv.x;
            r1.y = f1.y + (acc[mt][j][3] + bi_hi) * Sv.y;
            *(float2*)&out[off0] = r0;
            *(float2*)&out[off1] = r1;
        }
    }
}

// ===================== launch ==============================================
extern "C" void kernel_launch(void* const* d_in, const int* in_sizes, int n_in,
                              void* d_out, int out_size) {
    const float* front_x     = (const float*)d_in[0];
    const float* cross_x     = (const float*)d_in[1];
    const float* front_x_hat = (const float*)d_in[2];
    const float* Wq = (const float*)d_in[3];
    const float* bq = (const float*)d_in[4];
    const float* Wk = (const float*)d_in[5];
    const float* bk = (const float*)d_in[6];
    const float* Wv = (const float*)d_in[7];
    const float* bv = (const float*)d_in[8];
    const float* Wf = (const float*)d_in[9];
    const float* bf = (const float*)d_in[10];
    float* out = (float*)d_out;

    cudaFuncSetAttribute(conv_mma, cudaFuncAttributeMaxDynamicSharedMemorySize, 4 * STAGE);
    cudaFuncSetAttribute(mid_fused, cudaFuncAttributeMaxDynamicSharedMemorySize, MID_SMEM);

    prep_wv<<<256, 256>>>(Wv);

    gemm_qk<<<dim3(32, 2, 4), 256>>>(cross_x, front_x, Wq, bq, Wk, bk);

    mid_fused<<<SEG_PW, 256, MID_SMEM>>>(front_x, front_x_hat, bv, Wf);

    fill_xt_T<<<dim3(8, 64, 4), 256>>>();

    conv_mma<<<dim3(32, 2, 4), 256, 4 * STAGE>>>(front_x, bf, out);
}

// round 16
// speedup vs baseline: 1.2659x; 1.0764x over previous
#include <cuda_runtime.h>
#include <cuda_fp16.h>
#include <float.h>
#include <stdint.h>

#define Bb 4
#define Cc 256
#define C8 32
#define Hh 64
#define Ww 64
#define HW 4096

typedef unsigned long long ull;

// ===================== helpers =============================================
__device__ __forceinline__ uint32_t smem_u32(const void* p) {
    uint32_t a;
    asm("{ .reg .u64 t; cvta.to.shared.u64 t, %1; cvt.u32.u64 %0, t; }"
        : "=r"(a) : "l"(p));
    return a;
}
#define SWZ128(off) ((off) ^ (((off) >> 3) & 0x70))

__device__ __forceinline__ void ldsm_x4(uint32_t (&r)[4], uint32_t addr) {
    asm volatile("ldmatrix.sync.aligned.m8n8.x4.shared.b16 {%0,%1,%2,%3}, [%4];"
                 : "=r"(r[0]), "=r"(r[1]), "=r"(r[2]), "=r"(r[3]) : "r"(addr));
}

__device__ __forceinline__ void mma_f16(float (&d)[4], const uint32_t (&a)[4],
                                        uint32_t b0, uint32_t b1) {
    asm volatile(
        "mma.sync.aligned.m16n8k16.row.col.f32.f16.f16.f32 "
        "{%0,%1,%2,%3}, {%4,%5,%6,%7}, {%8,%9}, {%0,%1,%2,%3};"
        : "+f"(d[0]), "+f"(d[1]), "+f"(d[2]), "+f"(d[3])
        : "r"(a[0]), "r"(a[1]), "r"(a[2]), "r"(a[3]), "r"(b0), "r"(b1));
}

#define CP_ASYNC16(dst, src) \
    asm volatile("cp.async.cg.shared.global [%0], [%1], 16;" :: "r"(dst), "l"(src) : "memory")
#define CP_COMMIT()  asm volatile("cp.async.commit_group;" ::: "memory")
#define CP_WAIT2()   asm volatile("cp.async.wait_group 2;" ::: "memory")
#define CP_WAIT0()   asm volatile("cp.async.wait_group 0;" ::: "memory")

__device__ __forceinline__ uint32_t pack_h2(float a, float b) {
    __half2 h = __floats2half2_rn(a, b);
    return *(uint32_t*)&h;
}

// ---- packed dual-fp32 (sm_103) --------------------------------------------
__device__ __forceinline__ ull pack2(float lo, float hi) {
    ull r;
    asm("mov.b64 %0, {%1, %2};" : "=l"(r) : "f"(lo), "f"(hi));
    return r;
}
__device__ __forceinline__ void fma2(ull& d, ull a, ull b) {
    asm("fma.rn.f32x2 %0, %1, %2, %0;" : "+l"(d) : "l"(a), "l"(b));
}
__device__ __forceinline__ void unpack2(ull v, float& lo, float& hi) {
    asm("mov.b64 {%0, %1}, %2;" : "=f"(lo), "=f"(hi) : "l"(v));
}

// ===================== scratch =============================================
__device__ float g_q[Bb * C8 * HW];
__device__ float g_k[Bb * C8 * HW];
__device__ float g_vt[Bb * HW * Cc];          // NHWC value: [b][p][c]
__device__ float g_pmax[Bb * 4 * HW];
__device__ int   g_parg[Bb * 4 * HW];
__device__ float g_S[Bb * HW];
// NHWC fp16 single plane, zero halo (device globals zero-init; halo never written)
__device__ __half g_Xt[(size_t)Bb * 66 * 66 * 512];
// conv weights fp16 single plane: [tap9][o 256][c 512]
__device__ __half g_Wa[9 * 256 * 512];
// v weights fp16 single plane: [o 256][c 256]
__device__ __half g_Wv16[256 * 256];

// ===================== fused q+k projection (exact fp32, 128-px tiles) ======
__global__ __launch_bounds__(256) void gemm_qk(const float* __restrict__ cross_x,
                                               const float* __restrict__ front_x,
                                               const float* __restrict__ Wq,
                                               const float* __restrict__ bq,
                                               const float* __restrict__ Wk,
                                               const float* __restrict__ bk) {
    __shared__ float Xs[16][128];
    __shared__ float Ws[16][36];
    const int b   = blockIdx.z;
    const int sel = blockIdx.y;                 // 0 -> q, 1 -> k
    const int hw0 = blockIdx.x * 128;
    const int tid = threadIdx.x;
    const int hid = tid & 31;
    const int oid = tid >> 5;

    const float* X    = sel ? front_x : cross_x;
    const float* Wm   = sel ? Wk : Wq;
    const float* bias = sel ? bk : bq;
    float*       out  = sel ? g_k : g_q;

    const float* xb = X + (size_t)b * Cc * HW;
    float acc[4][4];
#pragma unroll
    for (int n = 0; n < 4; n++)
#pragma unroll
        for (int m = 0; m < 4; m++) acc[n][m] = 0.f;

    for (int c0 = 0; c0 < Cc; c0 += 16) {
        __syncthreads();
#pragma unroll
        for (int r = 0; r < 8; r++) {
            int idx = tid + r * 256;
            int cc = idx >> 7, h = idx & 127;
            Xs[cc][h] = xb[(size_t)(c0 + cc) * HW + hw0 + h];
        }
#pragma unroll
        for (int r = 0; r < 2; r++) {
            int idx = tid + r * 256;
            int cc = idx >> 5, o = idx & 31;
            Ws[cc][o] = Wm[(size_t)o * Cc + c0 + cc];
        }
        __syncthreads();
#pragma unroll
        for (int cc = 0; cc < 16; cc++) {
            float4 wv = *(const float4*)&Ws[cc][oid * 4];
            float4 xv = *(const float4*)&Xs[cc][hid * 4];
            float wa[4] = {wv.x, wv.y, wv.z, wv.w};
            float xa[4] = {xv.x, xv.y, xv.z, xv.w};
#pragma unroll
            for (int n = 0; n < 4; n++)
#pragma unroll
                for (int m = 0; m < 4; m++) acc[n][m] += wa[n] * xa[m];
        }
    }
#pragma unroll
    for (int n = 0; n < 4; n++) {
        int o = oid * 4 + n;
        float bi = bias[o];
        float4 res;
        res.x = acc[n][0] + bi;
        res.y = acc[n][1] + bi;
        res.z = acc[n][2] + bi;
        res.w = acc[n][3] + bi;
        *(float4*)&out[(size_t)b * C8 * HW + (size_t)o * HW + hw0 + hid * 4] = res;
    }
}

// ===================== fused mid kernel =====================================
// blockIdx.x ranges (long blocks first):
//   [0,256)      energy rowmax/argmax (exact fp32, f32x2 packed), 256 q/CTA
//   [256,512)    v projection (fp16 mma.sync)
//   [512,2560)   fill g_Xt front channels (fp16)
//   [2560,3072)  prep conv weights (fp16)
#define SEG_EN  256
#define SEG_VM  512
#define SEG_FI  2560
#define SEG_PW  3072
#define MID_SMEM 67584

__global__ __launch_bounds__(256) void mid_fused(const float* __restrict__ front_x,
                                                 const float* __restrict__ Xhat,
                                                 const float* __restrict__ bv,
                                                 const float* __restrict__ Wf) {
    extern __shared__ char dynsm[];
    const int tid  = threadIdx.x;
    const int bid  = blockIdx.x;

    if (bid < SEG_EN) {
        // ---------------- energy rowmax/argmax (exact fp32 via f32x2) -------
        float* ks = (float*)dynsm;                    // [32][128]
        const int jt = bid & 15;
        const int sp = (bid >> 4) & 3;
        const int b  = bid >> 6;
        const int j  = jt * 256 + tid;
        const float* qb = g_q + (size_t)b * C8 * HW;
        const float* kb = g_k + (size_t)b * C8 * HW;

        ull q2[32];
#pragma unroll
        for (int c = 0; c < 32; c++) {
            float qv = qb[c * HW + j];
            q2[c] = pack2(qv, qv);
        }

        float best = -FLT_MAX;
        int   barg = 0;
        const int i0base = sp * 1024;

        for (int it = 0; it < 8; it++) {
            int i0 = i0base + it * 128;
            __syncthreads();
#pragma unroll
            for (int p = 0; p < 16; p++) {
                int idx = tid + p * 256;
                int cc = idx >> 7, h = idx & 127;
                ks[cc * 128 + h] = kb[cc * HW + i0 + h];
            }
            __syncthreads();
#pragma unroll 4
            for (int ii = 0; ii < 128; ii += 4) {
                ull a01 = 0ULL, a23 = 0ULL;
#pragma unroll
                for (int c = 0; c < 32; c++) {
                    ulonglong2 kp = *(const ulonglong2*)&ks[c * 128 + ii];
                    fma2(a01, kp.x, q2[c]);   // keys ii, ii+1 (same order as scalar)
                    fma2(a23, kp.y, q2[c]);   // keys ii+2, ii+3
                }
                float e0, e1, e2, e3;
                unpack2(a01, e0, e1);
                unpack2(a23, e2, e3);
                if (e0 > best) { best = e0; barg = i0 + ii; }
                if (e1 > best) { best = e1; barg = i0 + ii + 1; }
                if (e2 > best) { best = e2; barg = i0 + ii + 2; }
                if (e3 > best) { best = e3; barg = i0 + ii + 3; }
            }
        }
        g_pmax[((size_t)b * 4 + sp) * HW + j] = best;
        g_parg[((size_t)b * 4 + sp) * HW + j] = barg;

    } else if (bid < SEG_VM) {
        // ---------------- v projection: fp16 mma.sync -----------------------
        const int id   = bid - SEG_EN;
        const int lane = tid & 31;
        const int wid  = tid >> 5;
        const int wm   = wid & 3;
        const int wn   = wid >> 2;
        const int n0   = (id & 31) * 128;
        const int m0   = ((id >> 5) & 1) * 128;
        const int b    = id >> 6;

        const uint32_t smbase = smem_u32(dynsm);
        const uint32_t tB = smbase;
        const uint32_t tA = smbase + 16384;

        float acc[2][8][4];
#pragma unroll
        for (int mt = 0; mt < 2; mt++)
#pragma unroll
            for (int j = 0; j < 8; j++)
#pragma unroll
                for (int e = 0; e < 4; e++) acc[mt][j][e] = 0.f;

        const int arow  = wm * 32 + (lane & 15);
        const int acolh = (lane >> 4) * 16;
        const int brow  = wn * 64 + (lane & 7) + ((lane >> 4) << 3);
        const int bcolh = ((lane >> 3) & 1) * 16;
        const int c2    = tid >> 5;

        for (int s = 0; s < 4; s++) {
            const int kc = s * 64;
            __syncthreads();
#pragma unroll
            for (int i = 0; i < 4; i++) {
                const int c = (i << 8) + tid;
                const int r = c >> 3, c16 = c & 7;
                uint32_t dst = tA + SWZ128((uint32_t)(r * 128 + c16 * 16));
                const __half* src = g_Wv16 + (size_t)(m0 + r) * 256 + kc + c16 * 8;
                CP_ASYNC16(dst, src);
            }
            CP_COMMIT();
#pragma unroll
            for (int cc = 0; cc < 4; cc++) {
                const int cp = c2 + 8 * cc;
                const size_t row0 = ((size_t)b * Cc + kc + 2 * cp) * HW + n0;
#pragma unroll
                for (int pb = 0; pb < 4; pb++) {
                    const int px = lane + 32 * pb;
                    float v0 = Xhat[row0 + px];
                    float v1 = Xhat[row0 + HW + px];
                    uint32_t off = SWZ128((uint32_t)(px * 128 + cp * 4));
                    *(uint32_t*)(dynsm + off) = pack_h2(v0, v1);
                }
            }
            CP_WAIT0();
            __syncthreads();

#pragma unroll
            for (int ks2 = 0; ks2 < 4; ks2++) {
                uint32_t ax[2][4], bx[4][4];
#pragma unroll
                for (int mt = 0; mt < 2; mt++) {
                    uint32_t off = SWZ128((uint32_t)((arow + mt * 16) * 128 + ks2 * 32 + acolh));
                    ldsm_x4(ax[mt], tA + off);
                }
#pragma unroll
                for (int j = 0; j < 4; j++) {
                    uint32_t off = SWZ128((uint32_t)((brow + j * 16) * 128 + ks2 * 32 + bcolh));
                    ldsm_x4(bx[j], tB + off);
                }
#pragma unroll
                for (int mt = 0; mt < 2; mt++)
#pragma unroll
                    for (int j = 0; j < 4; j++) {
                        mma_f16(acc[mt][2 * j],     ax[mt], bx[j][0], bx[j][1]);
                        mma_f16(acc[mt][2 * j + 1], ax[mt], bx[j][2], bx[j][3]);
                    }
            }
        }

        __syncthreads();
        float* smep = (float*)dynsm;
#pragma unroll
        for (int mt = 0; mt < 2; mt++) {
            const int o_lo = wm * 32 + mt * 16 + (lane >> 2);
            const int o_hi = o_lo + 8;
            const float bi_lo = bv[m0 + o_lo], bi_hi = bv[m0 + o_hi];
#pragma unroll
            for (int j = 0; j < 8; j++) {
                const int p = wn * 64 + j * 8 + 2 * (lane & 3);
                smep[p * 132 + o_lo]       = acc[mt][j][0] + bi_lo;
                smep[(p + 1) * 132 + o_lo] = acc[mt][j][1] + bi_lo;
                smep[p * 132 + o_hi]       = acc[mt][j][2] + bi_hi;
                smep[(p + 1) * 132 + o_hi] = acc[mt][j][3] + bi_hi;
            }
        }
        __syncthreads();
#pragma unroll
        for (int r = 0; r < 16; r++) {
            const int p = wid + 8 * r;
            float4 v = *(const float4*)&smep[p * 132 + lane * 4];
            *(float4*)&g_vt[((size_t)b * HW + n0 + p) * Cc + m0 + lane * 4] = v;
        }

    } else if (bid < SEG_FI) {
        // ---------------- fill g_Xt front channels (fp16) -------------------
        float* sm = (float*)dynsm;                    // [32][65]
        const int id = bid - SEG_VM;
        const int c0 = (id & 7) * 32;
        const int y  = (id >> 3) & 63;
        const int b  = id >> 9;
        const int x  = tid >> 2;
        const int g  = tid & 3;

#pragma unroll
        for (int pass = 0; pass < 8; pass++) {
            int idx = tid + pass * 256;
            int cc = idx >> 6, xx = idx & 63;
            sm[cc * 65 + xx] = front_x[((size_t)b * Cc + c0 + cc) * HW + y * Ww + xx];
        }
        __syncthreads();
        uint32_t hu[4];
#pragma unroll
        for (int e = 0; e < 4; e++)
            hu[e] = pack_h2(sm[(g * 8 + 2 * e) * 65 + x], sm[(g * 8 + 2 * e + 1) * 65 + x]);
        size_t base = ((size_t)(b * 66 + y + 1) * 66 + (x + 1)) * 512 + c0 + g * 8;
        *(uint4*)&g_Xt[base] = make_uint4(hu[0], hu[1], hu[2], hu[3]);

    } else {
        // ---------------- prep conv weights (fp16) --------------------------
        const int t = (bid - SEG_FI) * 256 + tid;     // < 131072
        const int o = t >> 9, i = t & 511;
#pragma unroll
        for (int k = 0; k < 9; k++) {
            float w = Wf[((size_t)o * 512 + i) * 9 + k];
            g_Wa[(((size_t)k) * 256 + o) * 512 + i] = __float2half_rn(w);
        }
    }
}

// ===================== fill T half + inline split-reduce =====================
__global__ __launch_bounds__(256) void fill_xt_T() {
    const int cx = blockIdx.x;                    // 0..7, channel chunk
    const int c0 = 256 + cx * 32;
    const int y  = blockIdx.y;
    const int b  = blockIdx.z;
    const int tid = threadIdx.x;
    const int x  = tid >> 2;
    const int g  = tid & 3;
    const int j  = y * Ww + x;

    // inline reduce of the 4 key-splits (same order/compare as before)
    float best = g_pmax[((size_t)b * 4) * HW + j];
    int   arg  = g_parg[((size_t)b * 4) * HW + j];
#pragma unroll
    for (int sp = 1; sp < 4; sp++) {
        float e = g_pmax[((size_t)b * 4 + sp) * HW + j];
        if (e > best) { best = e; arg = g_parg[((size_t)b * 4 + sp) * HW + j]; }
    }
    if (cx == 0 && g == 0) g_S[(size_t)b * HW + j] = best;

    const float* vp = g_vt + ((size_t)b * HW + arg) * Cc + (c0 - 256) + g * 8;
    float4 u0 = *(const float4*)vp;
    float4 u1 = *(const float4*)(vp + 4);

    uint32_t hu[4];
    hu[0] = pack_h2(u0.x, u0.y);
    hu[1] = pack_h2(u0.z, u0.w);
    hu[2] = pack_h2(u1.x, u1.y);
    hu[3] = pack_h2(u1.z, u1.w);
    size_t base = ((size_t)(b * 66 + y + 1) * 66 + (x + 1)) * 512 + c0 + g * 8;
    *(uint4*)&g_Xt[base] = make_uint4(hu[0], hu[1], hu[2], hu[3]);
}

__global__ void prep_wv(const float* __restrict__ Wv) {
    int t = blockIdx.x * 256 + threadIdx.x;
    g_Wv16[t] = __float2half_rn(Wv[t]);
}

// ===================== mma.sync conv3x3 (fp16 single-term) + epilogue =======
#define STAGE 32768
#define NCHUNK 72

__device__ __forceinline__ void stage_chunk(uint32_t stg, int s, int b, int y0, int m0) {
    const int tap = s >> 3, kc = (s & 7) * 64;
    const int dy = tap / 3, dx = tap % 3;
    const int tid = threadIdx.x;
#pragma unroll
    for (int i = 0; i < 8; i++) {
        const int t = i >> 2;                          // 0:X 1:W
        const int u = ((i & 3) << 8) + tid;            // 0..1023
        const int r = u >> 3, c16 = u & 7;
        uint32_t dst = stg + (uint32_t)(t * 16384) + SWZ128((uint32_t)(r * 128 + c16 * 16));
        const void* src;
        if (t == 0) {
            const int ry = r >> 6, x = r & 63;
            src = &g_Xt[(((size_t)(b * 66 + y0 + ry + dy) * 66) + (x + dx)) * 512
                        + kc + c16 * 8];
        } else {
            src = &g_Wa[(((size_t)tap * 256) + m0 + r) * 512 + kc + c16 * 8];
        }
        CP_ASYNC16(dst, src);
    }
    CP_COMMIT();
}

__global__ __launch_bounds__(256, 1) void conv_mma(const float* __restrict__ front_x,
                                                   const float* __restrict__ bf,
                                                   float* __restrict__ out) {
    extern __shared__ char dynsm[];
    const int tid  = threadIdx.x;
    const int lane = tid & 31;
    const int wid  = tid >> 5;
    const int wm   = wid & 3;
    const int wn   = wid >> 2;
    const int nt   = blockIdx.x;
    const int m0   = blockIdx.y * 128;
    const int b    = blockIdx.z;
    const int y0   = nt * 2;
    const int n0   = nt * 128;

    const uint32_t smbase = smem_u32(dynsm);

    float acc[2][8][4];
#pragma unroll
    for (int mt = 0; mt < 2; mt++)
#pragma unroll
        for (int j = 0; j < 8; j++)
#pragma unroll
            for (int e = 0; e < 4; e++) acc[mt][j][e] = 0.f;

    const int arow  = wm * 32 + (lane & 15);
    const int acolh = (lane >> 4) * 16;
    const int brow  = wn * 64 + (lane & 7) + ((lane >> 4) << 3);
    const int bcolh = ((lane >> 3) & 1) * 16;

    stage_chunk(smbase,             0, b, y0, m0);
    stage_chunk(smbase + STAGE,     1, b, y0, m0);
    stage_chunk(smbase + 2 * STAGE, 2, b, y0, m0);

    for (int s = 0; s < NCHUNK; s++) {
        CP_WAIT2();
        __syncthreads();
        if (s + 3 < NCHUNK)
            stage_chunk(smbase + ((s + 3) & 3) * STAGE, s + 3, b, y0, m0);

        const uint32_t base = smbase + (s & 3) * STAGE;
        const uint32_t tB = base;
        const uint32_t tA = base + 16384;

#pragma unroll
        for (int ks = 0; ks < 4; ks++) {
            uint32_t ax[2][4], bx[4][4];
#pragma unroll
            for (int mt = 0; mt < 2; mt++) {
                uint32_t off = SWZ128((uint32_t)((arow + mt * 16) * 128 + ks * 32 + acolh));
                ldsm_x4(ax[mt], tA + off);
            }
#pragma unroll
            for (int j = 0; j < 4; j++) {
                uint32_t off = SWZ128((uint32_t)((brow + j * 16) * 128 + ks * 32 + bcolh));
                ldsm_x4(bx[j], tB + off);
            }
#pragma unroll
            for (int mt = 0; mt < 2; mt++)
#pragma unroll
                for (int j = 0; j < 4; j++) {
                    mma_f16(acc[mt][2 * j],     ax[mt], bx[j][0], bx[j][1]);
                    mma_f16(acc[mt][2 * j + 1], ax[mt], bx[j][2], bx[j][3]);
                }
        }
        __syncthreads();
    }

    const float* Sb = g_S + (size_t)b * HW;
#pragma unroll
    for (int mt = 0; mt < 2; mt++) {
        const int o_lo = m0 + wm * 32 + mt * 16 + (lane >> 2);
        const int o_hi = o_lo + 8;
        const float bi_lo = bf[o_lo], bi_hi = bf[o_hi];
#pragma unroll
        for (int j = 0; j < 8; j++) {
            const int p = n0 + wn * 64 + j * 8 + 2 * (lane & 3);
            const float2 Sv = *(const float2*)&Sb[p];
            const size_t off0 = ((size_t)(b * Cc + o_lo)) * HW + p;
            const size_t off1 = ((size_t)(b * Cc + o_hi)) * HW + p;
            const float2 f0 = *(const float2*)&front_x[off0];
            const float2 f1 = *(const float2*)&front_x[off1];
            float2 r0, r1;
            r0.x = f0.x + (acc[mt][j][0] + bi_lo) * Sv.x;
            r0.y = f0.y + (acc[mt][j][1] + bi_lo) * Sv.y;
            r1.x = f1.x + (acc[mt][j][2] + bi_hi) * Sv.x;
            r1.y = f1.y + (acc[mt][j][3] + bi_hi) * Sv.y;
            *(float2*)&out[off0] = r0;
            *(float2*)&out[off1] = r1;
        }
    }
}

// ===================== launch ==============================================
extern "C" void kernel_launch(void* const* d_in, const int* in_sizes, int n_in,
                              void* d_out, int out_size) {
    const float* front_x     = (const float*)d_in[0];
    const float* cross_x     = (const float*)d_in[1];
    const float* front_x_hat = (const float*)d_in[2];
    const float* Wq = (const float*)d_in[3];
    const float* bq = (const float*)d_in[4];
    const float* Wk = (const float*)d_in[5];
    const float* bk = (const float*)d_in[6];
    const float* Wv = (const float*)d_in[7];
    const float* bv = (const float*)d_in[8];
    const float* Wf = (const float*)d_in[9];
    const float* bf = (const float*)d_in[10];
    float* out = (float*)d_out;

    cudaFuncSetAttribute(conv_mma, cudaFuncAttributeMaxDynamicSharedMemorySize, 4 * STAGE);
    cudaFuncSetAttribute(mid_fused, cudaFuncAttributeMaxDynamicSharedMemorySize, MID_SMEM);

    prep_wv<<<256, 256>>>(Wv);

    gemm_qk<<<dim3(32, 2, 4), 256>>>(cross_x, front_x, Wq, bq, Wk, bk);

    mid_fused<<<SEG_PW, 256, MID_SMEM>>>(front_x, front_x_hat, bv, Wf);

    fill_xt_T<<<dim3(8, 64, 4), 256>>>();

    conv_mma<<<dim3(32, 2, 4), 256, 4 * STAGE>>>(front_x, bf, out);
}